// round 3
// baseline (speedup 1.0000x reference)
#include <cuda_runtime.h>

// PlaneEmbeddingNetwork fused kernel for GB300 (sm_103a), R3.
// 2 threads per face (one per head), adjacent lanes, lane-local token order.
// R3 change: ALL weights live in __constant__ memory (9.7KB). Warp-uniform
// constant loads use the const-cache/uniform port, bypassing the l1tex data
// stage that was the R2 bottleneck (broadcast LDS.128 = 4 wavefronts each).

typedef unsigned long long u64;

__device__ __forceinline__ u64 fma2(u64 a, u64 b, u64 c) {
    u64 d;
    asm("fma.rn.f32x2 %0, %1, %2, %3;" : "=l"(d) : "l"(a), "l"(b), "l"(c));
    return d;
}
__device__ __forceinline__ u64 add2(u64 a, u64 b) {
    u64 d;
    asm("add.rn.f32x2 %0, %1, %2;" : "=l"(d) : "l"(a), "l"(b));
    return d;
}
__device__ __forceinline__ u64 mul2(u64 a, u64 b) {
    u64 d;
    asm("mul.rn.f32x2 %0, %1, %2;" : "=l"(d) : "l"(a), "l"(b));
    return d;
}
__device__ __forceinline__ u64 pack2(float x, float y) {
    u64 r;
    asm("mov.b64 %0, {%1, %2};" : "=l"(r) : "f"(x), "f"(y));
    return r;
}
__device__ __forceinline__ float2 unpack2(u64 v) {
    float2 f;
    asm("mov.b64 {%0, %1}, %2;" : "=f"(f.x), "=f"(f.y) : "l"(v));
    return f;
}
__device__ __forceinline__ float getc(float4 v, int c) {
    return c == 0 ? v.x : (c == 1 ? v.y : (c == 2 ? v.z : v.w));
}

// Packed weight layout (floats):
//   [0,768)      w_in   [16][48]  (cols: 0-15 q, 16-31 k, 32-47 v)
//   [768,816)    b_in   [48]
//   [816,1328)   W2     [16][32]  (fused w_out @ fc_w)
//   [1328,1360)  b2     [32]      (fc_b + b_out @ fc_w)
//   [1360,2384)  fco_w  [32][32]
//   [2384,2416)  fco_b  [32]
#define OFF_WIN  0
#define OFF_BIN  768
#define OFF_W2   816
#define OFF_B2   1328
#define OFF_FCO  1360
#define OFF_FCOB 2384
#define PACK_N   2416

__device__   __align__(16) float g_pack[PACK_N];
__constant__ __align__(16) float c_pack[PACK_N];

__global__ void prep_kernel(const float* __restrict__ w_in, const float* __restrict__ b_in,
                            const float* __restrict__ w_out, const float* __restrict__ b_out,
                            const float* __restrict__ fc_w, const float* __restrict__ fc_b,
                            const float* __restrict__ fco_w, const float* __restrict__ fco_b) {
    int i = threadIdx.x;   // 1024 threads
    if (i < 768) g_pack[OFF_WIN + i] = w_in[i];
    if (i < 48)  g_pack[OFF_BIN + i] = b_in[i];
    if (i < 512) {
        int d = i >> 5, j = i & 31;
        float s = 0.f;
#pragma unroll
        for (int e = 0; e < 16; e++) s += w_out[d * 16 + e] * fc_w[e * 32 + j];
        g_pack[OFF_W2 + i] = s;
    }
    if (i < 32) {
        float s = fc_b[i];
#pragma unroll
        for (int e = 0; e < 16; e++) s += b_out[e] * fc_w[e * 32 + i];
        g_pack[OFF_B2 + i] = s;
    }
    if (i < 1024) g_pack[OFF_FCO + i] = fco_w[i];
    if (i < 32)   g_pack[OFF_FCOB + i] = fco_b[i];
}

__global__ void __launch_bounds__(128)
face_kernel(const float* __restrict__ node, const int* __restrict__ fids,
            float* __restrict__ out, int F) {
    int tid = threadIdx.x;
    int gt = blockIdx.x * 128 + tid;
    int face = gt >> 1;
    int h = gt & 1;                 // head index (0 or 1)
    bool valid = face < F;
    if (!valid) face = F - 1;       // clamp: tail lanes still participate in shuffles

    // ---- gather: each lane loads only its OWN 2 tokens (lane-local order) ----
    int4 I = *(const int4*)(fids + 4ll * face);
    int ida = h ? I.z : I.x;
    int idb = h ? I.w : I.y;
    float4 XA[4], XB[4];
    {
        const float4* ra = (const float4*)(node + 16ll * ida);
        const float4* rb = (const float4*)(node + 16ll * idb);
        XA[0] = ra[0]; XA[1] = ra[1]; XA[2] = ra[2]; XA[3] = ra[3];
        XB[0] = rb[0]; XB[1] = rb[1]; XB[2] = rb[2]; XB[3] = rb[3];
    }

    // Lane-local token order: 0 = own_a, 1 = own_b, 2 = partner_a, 3 = partner_b.
    // Attention is permutation-invariant per head, so lanes may disagree on order.

    // ---- phase 1a: q,k for all 4 tokens (own head), d-outer for weight reuse ----
    u64 q2[4][4], k2[4][4];
    {
        const u64* bq = (const u64*)(c_pack + OFF_BIN + 8 * h);
        const u64* bk = (const u64*)(c_pack + OFF_BIN + 16 + 8 * h);
#pragma unroll
        for (int t = 0; t < 4; t++)
#pragma unroll
            for (int j = 0; j < 4; j++) { q2[t][j] = bq[j]; k2[t][j] = bk[j]; }
    }
    {
        const float* wq = c_pack + OFF_WIN + 8 * h;
        const float* wk = c_pack + OFF_WIN + 16 + 8 * h;
#pragma unroll
        for (int d = 0; d < 16; d++) {
            ulonglong2 wq0 = *(const ulonglong2*)(wq + d * 48);
            ulonglong2 wq1 = *(const ulonglong2*)(wq + d * 48 + 4);
            ulonglong2 wk0 = *(const ulonglong2*)(wk + d * 48);
            ulonglong2 wk1 = *(const ulonglong2*)(wk + d * 48 + 4);
            float xa = getc(XA[d >> 2], d & 3);
            float xb = getc(XB[d >> 2], d & 3);
            float fa = __shfl_xor_sync(0xffffffffu, xa, 1);
            float fb = __shfl_xor_sync(0xffffffffu, xb, 1);
            u64 xt[4] = {pack2(xa, xa), pack2(xb, xb), pack2(fa, fa), pack2(fb, fb)};
#pragma unroll
            for (int t = 0; t < 4; t++) {
                q2[t][0] = fma2(xt[t], wq0.x, q2[t][0]);
                q2[t][1] = fma2(xt[t], wq0.y, q2[t][1]);
                q2[t][2] = fma2(xt[t], wq1.x, q2[t][2]);
                q2[t][3] = fma2(xt[t], wq1.y, q2[t][3]);
                k2[t][0] = fma2(xt[t], wk0.x, k2[t][0]);
                k2[t][1] = fma2(xt[t], wk0.y, k2[t][1]);
                k2[t][2] = fma2(xt[t], wk1.x, k2[t][2]);
                k2[t][3] = fma2(xt[t], wk1.y, k2[t][3]);
            }
        }
    }

    // ---- scores + softmax (own head, 4x4, lane-local token order) ----
    float att[4][4];
    const float RS = 0.35355339059327373f;  // 1/sqrt(8)
#pragma unroll
    for (int qi = 0; qi < 4; qi++) {
#pragma unroll
        for (int ki = 0; ki < 4; ki++) {
            u64 a = fma2(q2[qi][0], k2[ki][0], 0ull);
            a = fma2(q2[qi][1], k2[ki][1], a);
            a = fma2(q2[qi][2], k2[ki][2], a);
            a = fma2(q2[qi][3], k2[ki][3], a);
            float2 p = unpack2(a);
            att[qi][ki] = (p.x + p.y) * RS;
        }
        float m = fmaxf(fmaxf(att[qi][0], att[qi][1]), fmaxf(att[qi][2], att[qi][3]));
        float e0 = __expf(att[qi][0] - m);
        float e1 = __expf(att[qi][1] - m);
        float e2 = __expf(att[qi][2] - m);
        float e3 = __expf(att[qi][3] - m);
        float inv = 1.0f / (e0 + e1 + e2 + e3);
        att[qi][0] = e0 * inv; att[qi][1] = e1 * inv;
        att[qi][2] = e2 * inv; att[qi][3] = e3 * inv;
    }

    // ---- phase 1b: v for all 4 tokens (own head), d-outer ----
    u64 v2[4][4];
    {
        const u64* bv = (const u64*)(c_pack + OFF_BIN + 32 + 8 * h);
#pragma unroll
        for (int t = 0; t < 4; t++)
#pragma unroll
            for (int j = 0; j < 4; j++) v2[t][j] = bv[j];
    }
    {
        const float* wv = c_pack + OFF_WIN + 32 + 8 * h;
#pragma unroll
        for (int d = 0; d < 16; d++) {
            ulonglong2 wv0 = *(const ulonglong2*)(wv + d * 48);
            ulonglong2 wv1 = *(const ulonglong2*)(wv + d * 48 + 4);
            float xa = getc(XA[d >> 2], d & 3);
            float xb = getc(XB[d >> 2], d & 3);
            float fa = __shfl_xor_sync(0xffffffffu, xa, 1);
            float fb = __shfl_xor_sync(0xffffffffu, xb, 1);
            u64 xt[4] = {pack2(xa, xa), pack2(xb, xb), pack2(fa, fa), pack2(fb, fb)};
#pragma unroll
            for (int t = 0; t < 4; t++) {
                v2[t][0] = fma2(xt[t], wv0.x, v2[t][0]);
                v2[t][1] = fma2(xt[t], wv0.y, v2[t][1]);
                v2[t][2] = fma2(xt[t], wv1.x, v2[t][2]);
                v2[t][3] = fma2(xt[t], wv1.y, v2[t][3]);
            }
        }
    }

    // ---- o = attn @ v for all 4 local query tokens (own head half: 8 dims) ----
    u64 o2[4][4];
#pragma unroll
    for (int qi = 0; qi < 4; qi++) {
#pragma unroll
        for (int j = 0; j < 4; j++) o2[qi][j] = 0ull;
#pragma unroll
        for (int s = 0; s < 4; s++) {
            u64 a2 = pack2(att[qi][s], att[qi][s]);
#pragma unroll
            for (int j = 0; j < 4; j++) o2[qi][j] = fma2(a2, v2[s][j], o2[qi][j]);
        }
    }

    // ---- exchange o halves: I keep my 2 own tokens, full 16 dims ----
    u64 olo[2][4], ohi[2][4];   // dims 0-7 and 8-15 of my own 2 tokens
#pragma unroll
    for (int t = 0; t < 2; t++)
#pragma unroll
        for (int j = 0; j < 4; j++) {
            u64 rcv = __shfl_xor_sync(0xffffffffu, o2[t + 2][j], 1);
            u64 own = o2[t][j];
            olo[t][j] = h ? rcv : own;
            ohi[t][j] = h ? own : rcv;
        }

    // ---- W2: h_tok = o_full @ W2 + b2 for my 2 tokens (d-outer, weight reuse) ----
    u64 hA[16], hB[16];
    {
        const u64* b2p = (const u64*)(c_pack + OFF_B2);
#pragma unroll
        for (int j = 0; j < 16; j++) { hA[j] = b2p[j]; hB[j] = b2p[j]; }
    }
#pragma unroll
    for (int d = 0; d < 8; d++) {
        const ulonglong2* wr = (const ulonglong2*)(c_pack + OFF_W2 + d * 32);
        float2 pa = unpack2(olo[0][d >> 1]);
        float2 pb = unpack2(olo[1][d >> 1]);
        float x0 = (d & 1) ? pa.y : pa.x;
        float x1 = (d & 1) ? pb.y : pb.x;
        u64 x0p = pack2(x0, x0), x1p = pack2(x1, x1);
#pragma unroll
        for (int j4 = 0; j4 < 8; j4++) {
            ulonglong2 w = wr[j4];
            hA[2 * j4]     = fma2(x0p, w.x, hA[2 * j4]);
            hA[2 * j4 + 1] = fma2(x0p, w.y, hA[2 * j4 + 1]);
            hB[2 * j4]     = fma2(x1p, w.x, hB[2 * j4]);
            hB[2 * j4 + 1] = fma2(x1p, w.y, hB[2 * j4 + 1]);
        }
    }
#pragma unroll
    for (int d = 8; d < 16; d++) {
        const ulonglong2* wr = (const ulonglong2*)(c_pack + OFF_W2 + d * 32);
        float2 pa = unpack2(ohi[0][(d - 8) >> 1]);
        float2 pb = unpack2(ohi[1][(d - 8) >> 1]);
        float x0 = (d & 1) ? pa.y : pa.x;
        float x1 = (d & 1) ? pb.y : pb.x;
        u64 x0p = pack2(x0, x0), x1p = pack2(x1, x1);
#pragma unroll
        for (int j4 = 0; j4 < 8; j4++) {
            ulonglong2 w = wr[j4];
            hA[2 * j4]     = fma2(x0p, w.x, hA[2 * j4]);
            hA[2 * j4 + 1] = fma2(x0p, w.y, hA[2 * j4 + 1]);
            hB[2 * j4]     = fma2(x1p, w.x, hB[2 * j4]);
            hB[2 * j4 + 1] = fma2(x1p, w.y, hB[2 * j4 + 1]);
        }
    }

    // ---- relu + pool over my 2 tokens, exchange partial sums, scale by 1/4 ----
    u64 pool[16];
    const u64 QUARTER = pack2(0.25f, 0.25f);
#pragma unroll
    for (int j = 0; j < 16; j++) {
        float2 a = unpack2(hA[j]);
        float2 b = unpack2(hB[j]);
        float px = fmaxf(a.x, 0.f) + fmaxf(b.x, 0.f);
        float py = fmaxf(a.y, 0.f) + fmaxf(b.y, 0.f);
        u64 p = pack2(px, py);
        u64 q = __shfl_xor_sync(0xffffffffu, p, 1);
        pool[j] = mul2(add2(p, q), QUARTER);   // commutative add -> identical both lanes
    }

    // ---- fco: out[16h .. 16h+16) = pooled @ fco_w + fco_b ----
    u64 acc[8];
    {
        const u64* fb = (const u64*)(c_pack + OFF_FCOB + 16 * h);
#pragma unroll
        for (int p = 0; p < 8; p++) acc[p] = fb[p];
    }
    const float* fch = c_pack + OFF_FCO + 16 * h;
#pragma unroll
    for (int e = 0; e < 32; e++) {
        float2 pp = unpack2(pool[e >> 1]);
        float pe = (e & 1) ? pp.y : pp.x;
        u64 pe2 = pack2(pe, pe);
        const ulonglong2* fr = (const ulonglong2*)(fch + e * 32);
#pragma unroll
        for (int p4 = 0; p4 < 4; p4++) {
            ulonglong2 w = fr[p4];
            acc[2 * p4]     = fma2(pe2, w.x, acc[2 * p4]);
            acc[2 * p4 + 1] = fma2(pe2, w.y, acc[2 * p4 + 1]);
        }
    }

    if (valid) {
        float* op = out + 32ll * face + 16 * h;
#pragma unroll
        for (int p4 = 0; p4 < 4; p4++) {
            float2 a = unpack2(acc[2 * p4]);
            float2 b = unpack2(acc[2 * p4 + 1]);
            *(float4*)(op + 4 * p4) = make_float4(a.x, a.y, b.x, b.y);
        }
    }
}

extern "C" void kernel_launch(void* const* d_in, const int* in_sizes, int n_in,
                              void* d_out, int out_size) {
    const float* node  = (const float*)d_in[0];
    const int*   fids  = (const int*)d_in[1];
    const float* w_in  = (const float*)d_in[2];
    const float* b_in  = (const float*)d_in[3];
    const float* w_out = (const float*)d_in[4];
    const float* b_out = (const float*)d_in[5];
    const float* fc_w  = (const float*)d_in[6];
    const float* fc_b  = (const float*)d_in[7];
    const float* fco_w = (const float*)d_in[8];
    const float* fco_b = (const float*)d_in[9];

    int F = in_sizes[1] / 4;

    prep_kernel<<<1, 1024>>>(w_in, b_in, w_out, b_out, fc_w, fc_b, fco_w, fco_b);

    // Populate the constant bank from the device staging buffer (D2D memcpy
    // node in the graph; ordered after prep_kernel on the same stream).
    void* g_addr = nullptr;
    cudaGetSymbolAddress(&g_addr, g_pack);
    cudaMemcpyToSymbolAsync(c_pack, g_addr, PACK_N * sizeof(float), 0,
                            cudaMemcpyDeviceToDevice, 0);

    long long threads = 2ll * F;
    int blocks = (int)((threads + 127) / 128);
    face_kernel<<<blocks, 128>>>(node, fids, (float*)d_out, F);
}

// round 4
// speedup vs baseline: 1.1637x; 1.1637x over previous
#include <cuda_runtime.h>

// PlaneEmbeddingNetwork fused kernel for GB300 (sm_103a), R4.
// Head h = warpId & 1  -> ALL weight addresses are warp-uniform -> constant
// loads take the uniform path (LDCU -> UR, floor 1) instead of the half-rate
// LDC GPR port that sank R3, and instead of the l1tex LDS traffic that bounded
// R2. Face pair = same lane in paired warps (w, w^1); the two tiny exchanges
// (o halves, pool partials) go through conflict-free shared buffers.

typedef unsigned long long u64;

__device__ __forceinline__ u64 fma2(u64 a, u64 b, u64 c) {
    u64 d;
    asm("fma.rn.f32x2 %0, %1, %2, %3;" : "=l"(d) : "l"(a), "l"(b), "l"(c));
    return d;
}
__device__ __forceinline__ u64 add2(u64 a, u64 b) {
    u64 d;
    asm("add.rn.f32x2 %0, %1, %2;" : "=l"(d) : "l"(a), "l"(b));
    return d;
}
__device__ __forceinline__ u64 mul2(u64 a, u64 b) {
    u64 d;
    asm("mul.rn.f32x2 %0, %1, %2;" : "=l"(d) : "l"(a), "l"(b));
    return d;
}
__device__ __forceinline__ u64 pack2(float x, float y) {
    u64 r;
    asm("mov.b64 %0, {%1, %2};" : "=l"(r) : "f"(x), "f"(y));
    return r;
}
__device__ __forceinline__ float2 unpack2(u64 v) {
    float2 f;
    asm("mov.b64 {%0, %1}, %2;" : "=f"(f.x), "=f"(f.y) : "l"(v));
    return f;
}
__device__ __forceinline__ float getc(float4 v, int c) {
    return c == 0 ? v.x : (c == 1 ? v.y : (c == 2 ? v.z : v.w));
}

// Packed weight layout (floats):
//   [0,768)      w_in   [16][48]  (cols: 0-15 q, 16-31 k, 32-47 v)
//   [768,816)    b_in   [48]
//   [816,1328)   W2     [16][32]  (fused w_out @ fc_w)
//   [1328,1360)  b2     [32]      (fc_b + b_out @ fc_w)
//   [1360,2384)  fco_w  [32][32]
//   [2384,2416)  fco_b  [32]
#define OFF_WIN  0
#define OFF_BIN  768
#define OFF_W2   816
#define OFF_B2   1328
#define OFF_FCO  1360
#define OFF_FCOB 2384
#define PACK_N   2416

__device__   __align__(16) float g_pack[PACK_N];
__constant__ __align__(16) float c_pack[PACK_N];

__global__ void prep_kernel(const float* __restrict__ w_in, const float* __restrict__ b_in,
                            const float* __restrict__ w_out, const float* __restrict__ b_out,
                            const float* __restrict__ fc_w, const float* __restrict__ fc_b,
                            const float* __restrict__ fco_w, const float* __restrict__ fco_b) {
    int i = threadIdx.x;   // 1024 threads
    if (i < 768) g_pack[OFF_WIN + i] = w_in[i];
    if (i < 48)  g_pack[OFF_BIN + i] = b_in[i];
    if (i < 512) {
        int d = i >> 5, j = i & 31;
        float s = 0.f;
#pragma unroll
        for (int e = 0; e < 16; e++) s += w_out[d * 16 + e] * fc_w[e * 32 + j];
        g_pack[OFF_W2 + i] = s;
    }
    if (i < 32) {
        float s = fc_b[i];
#pragma unroll
        for (int e = 0; e < 16; e++) s += b_out[e] * fc_w[e * 32 + i];
        g_pack[OFF_B2 + i] = s;
    }
    if (i < 1024) g_pack[OFF_FCO + i] = fco_w[i];
    if (i < 32)   g_pack[OFF_FCOB + i] = fco_b[i];
}

__global__ void __launch_bounds__(128)
face_kernel(const float* __restrict__ node, const int* __restrict__ fids,
            float* __restrict__ out, int F) {
    // Exchange buffers, [j][warp][lane]: lane-stride 8B -> conflict-free.
    __shared__ u64 obuf[8][4][32];
    __shared__ u64 pbuf[16][4][32];

    int lane = threadIdx.x & 31;
    int w = threadIdx.x >> 5;       // 0..3
    int h = w & 1;                  // head, WARP-UNIFORM
    int pairIdx = w >> 1;           // 0..1

    int face = blockIdx.x * 64 + pairIdx * 32 + lane;
    bool valid = face < F;
    if (!valid) face = F - 1;       // clamp; still runs barriers/exchanges

    // ---- gather: all 4 token rows (global token order, both warps identical) ----
    int4 I = *(const int4*)(fids + 4ll * face);
    int ids[4] = {I.x, I.y, I.z, I.w};
    float4 X[4][4];
#pragma unroll
    for (int t = 0; t < 4; t++) {
        const float4* r = (const float4*)(node + 16ll * ids[t]);
        X[t][0] = r[0]; X[t][1] = r[1]; X[t][2] = r[2]; X[t][3] = r[3];
    }

    // ---- phase 1a: q,k for all 4 tokens (own head), d-outer; weights uniform ----
    u64 q2[4][4], k2[4][4];
    {
        const u64* bq = (const u64*)(c_pack + OFF_BIN + 8 * h);
        const u64* bk = (const u64*)(c_pack + OFF_BIN + 16 + 8 * h);
#pragma unroll
        for (int t = 0; t < 4; t++)
#pragma unroll
            for (int j = 0; j < 4; j++) { q2[t][j] = bq[j]; k2[t][j] = bk[j]; }
    }
#pragma unroll
    for (int d = 0; d < 16; d++) {
        const float* wq = c_pack + OFF_WIN + d * 48 + 8 * h;
        ulonglong2 wq0 = *(const ulonglong2*)(wq);
        ulonglong2 wq1 = *(const ulonglong2*)(wq + 4);
        ulonglong2 wk0 = *(const ulonglong2*)(wq + 16);
        ulonglong2 wk1 = *(const ulonglong2*)(wq + 20);
#pragma unroll
        for (int t = 0; t < 4; t++) {
            float xv = getc(X[t][d >> 2], d & 3);
            u64 x2 = pack2(xv, xv);
            q2[t][0] = fma2(x2, wq0.x, q2[t][0]);
            q2[t][1] = fma2(x2, wq0.y, q2[t][1]);
            q2[t][2] = fma2(x2, wq1.x, q2[t][2]);
            q2[t][3] = fma2(x2, wq1.y, q2[t][3]);
            k2[t][0] = fma2(x2, wk0.x, k2[t][0]);
            k2[t][1] = fma2(x2, wk0.y, k2[t][1]);
            k2[t][2] = fma2(x2, wk1.x, k2[t][2]);
            k2[t][3] = fma2(x2, wk1.y, k2[t][3]);
        }
    }

    // ---- scores + softmax (own head, 4x4, global token order) ----
    float att[4][4];
    const float RS = 0.35355339059327373f;  // 1/sqrt(8)
#pragma unroll
    for (int qi = 0; qi < 4; qi++) {
#pragma unroll
        for (int ki = 0; ki < 4; ki++) {
            u64 a = fma2(q2[qi][0], k2[ki][0], 0ull);
            a = fma2(q2[qi][1], k2[ki][1], a);
            a = fma2(q2[qi][2], k2[ki][2], a);
            a = fma2(q2[qi][3], k2[ki][3], a);
            float2 p = unpack2(a);
            att[qi][ki] = (p.x + p.y) * RS;
        }
        float m = fmaxf(fmaxf(att[qi][0], att[qi][1]), fmaxf(att[qi][2], att[qi][3]));
        float e0 = __expf(att[qi][0] - m);
        float e1 = __expf(att[qi][1] - m);
        float e2 = __expf(att[qi][2] - m);
        float e3 = __expf(att[qi][3] - m);
        float inv = 1.0f / (e0 + e1 + e2 + e3);
        att[qi][0] = e0 * inv; att[qi][1] = e1 * inv;
        att[qi][2] = e2 * inv; att[qi][3] = e3 * inv;
    }

    // ---- phase 1b: v for all 4 tokens (own head) ----
    u64 v2[4][4];
    {
        const u64* bv = (const u64*)(c_pack + OFF_BIN + 32 + 8 * h);
#pragma unroll
        for (int t = 0; t < 4; t++)
#pragma unroll
            for (int j = 0; j < 4; j++) v2[t][j] = bv[j];
    }
#pragma unroll
    for (int d = 0; d < 16; d++) {
        const float* wv = c_pack + OFF_WIN + d * 48 + 32 + 8 * h;
        ulonglong2 wv0 = *(const ulonglong2*)(wv);
        ulonglong2 wv1 = *(const ulonglong2*)(wv + 4);
#pragma unroll
        for (int t = 0; t < 4; t++) {
            float xv = getc(X[t][d >> 2], d & 3);
            u64 x2 = pack2(xv, xv);
            v2[t][0] = fma2(x2, wv0.x, v2[t][0]);
            v2[t][1] = fma2(x2, wv0.y, v2[t][1]);
            v2[t][2] = fma2(x2, wv1.x, v2[t][2]);
            v2[t][3] = fma2(x2, wv1.y, v2[t][3]);
        }
    }

    // ---- o = attn @ v for all 4 query tokens (own head half: 8 dims) ----
    u64 o2[4][4];
#pragma unroll
    for (int qi = 0; qi < 4; qi++) {
#pragma unroll
        for (int j = 0; j < 4; j++) o2[qi][j] = 0ull;
#pragma unroll
        for (int s = 0; s < 4; s++) {
            u64 a2 = pack2(att[qi][s], att[qi][s]);
#pragma unroll
            for (int j = 0; j < 4; j++) o2[qi][j] = fma2(a2, v2[s][j], o2[qi][j]);
        }
    }

    // ---- cross-warp exchange: I own tokens {2h, 2h+1}; write partner's ----
    int pt = h ? 0 : 2;   // partner's token base (global order)
#pragma unroll
    for (int j = 0; j < 4; j++) {
        obuf[j][w][lane]     = o2[pt][j];
        obuf[4 + j][w][lane] = o2[pt + 1][j];
    }
    __syncthreads();
    u64 oo0[4], oo1[4];   // partner-head half of my lower/upper token
#pragma unroll
    for (int j = 0; j < 4; j++) {
        oo0[j] = obuf[j][w ^ 1][lane];
        oo1[j] = obuf[4 + j][w ^ 1][lane];
    }

    // Assemble full-o for my 2 tokens: lo = head0 dims 0-7, hi = head1 dims 8-15.
    int mt = 2 * h;
    u64 Alo[4], Ahi[4], Blo[4], Bhi[4];
#pragma unroll
    for (int j = 0; j < 4; j++) {
        Alo[j] = h ? oo0[j] : o2[mt][j];
        Ahi[j] = h ? o2[mt][j] : oo0[j];
        Blo[j] = h ? oo1[j] : o2[mt + 1][j];
        Bhi[j] = h ? o2[mt + 1][j] : oo1[j];
    }

    // ---- W2: h_tok = o_full @ W2 + b2 for my 2 tokens (d-outer, uniform weights) ----
    u64 hA[16], hB[16];
    {
        const u64* b2p = (const u64*)(c_pack + OFF_B2);
#pragma unroll
        for (int j = 0; j < 16; j++) { hA[j] = b2p[j]; hB[j] = b2p[j]; }
    }
#pragma unroll
    for (int d = 0; d < 8; d++) {
        const ulonglong2* wr = (const ulonglong2*)(c_pack + OFF_W2 + d * 32);
        float2 pa = unpack2(Alo[d >> 1]);
        float2 pb = unpack2(Blo[d >> 1]);
        float x0 = (d & 1) ? pa.y : pa.x;
        float x1 = (d & 1) ? pb.y : pb.x;
        u64 x0p = pack2(x0, x0), x1p = pack2(x1, x1);
#pragma unroll
        for (int j4 = 0; j4 < 8; j4++) {
            ulonglong2 ww = wr[j4];
            hA[2 * j4]     = fma2(x0p, ww.x, hA[2 * j4]);
            hA[2 * j4 + 1] = fma2(x0p, ww.y, hA[2 * j4 + 1]);
            hB[2 * j4]     = fma2(x1p, ww.x, hB[2 * j4]);
            hB[2 * j4 + 1] = fma2(x1p, ww.y, hB[2 * j4 + 1]);
        }
    }
#pragma unroll
    for (int d = 8; d < 16; d++) {
        const ulonglong2* wr = (const ulonglong2*)(c_pack + OFF_W2 + d * 32);
        float2 pa = unpack2(Ahi[(d - 8) >> 1]);
        float2 pb = unpack2(Bhi[(d - 8) >> 1]);
        float x0 = (d & 1) ? pa.y : pa.x;
        float x1 = (d & 1) ? pb.y : pb.x;
        u64 x0p = pack2(x0, x0), x1p = pack2(x1, x1);
#pragma unroll
        for (int j4 = 0; j4 < 8; j4++) {
            ulonglong2 ww = wr[j4];
            hA[2 * j4]     = fma2(x0p, ww.x, hA[2 * j4]);
            hA[2 * j4 + 1] = fma2(x0p, ww.y, hA[2 * j4 + 1]);
            hB[2 * j4]     = fma2(x1p, ww.x, hB[2 * j4]);
            hB[2 * j4 + 1] = fma2(x1p, ww.y, hB[2 * j4 + 1]);
        }
    }

    // ---- relu + partial pool over my 2 tokens; exchange; scale by 1/4 ----
    u64 p[16];
#pragma unroll
    for (int j = 0; j < 16; j++) {
        float2 a = unpack2(hA[j]);
        float2 b = unpack2(hB[j]);
        p[j] = pack2(fmaxf(a.x, 0.f) + fmaxf(b.x, 0.f),
                     fmaxf(a.y, 0.f) + fmaxf(b.y, 0.f));
        pbuf[j][w][lane] = p[j];
    }
    __syncthreads();
    u64 pool[16];
    const u64 QUARTER = pack2(0.25f, 0.25f);
#pragma unroll
    for (int j = 0; j < 16; j++)
        pool[j] = mul2(add2(p[j], pbuf[j][w ^ 1][lane]), QUARTER);

    // ---- fco: out[16h .. 16h+16) = pooled @ fco_w + fco_b (uniform weights) ----
    u64 acc[8];
    {
        const u64* fb = (const u64*)(c_pack + OFF_FCOB + 16 * h);
#pragma unroll
        for (int q = 0; q < 8; q++) acc[q] = fb[q];
    }
    const float* fch = c_pack + OFF_FCO + 16 * h;
#pragma unroll
    for (int e = 0; e < 32; e++) {
        float2 pp = unpack2(pool[e >> 1]);
        float pe = (e & 1) ? pp.y : pp.x;
        u64 pe2 = pack2(pe, pe);
        const ulonglong2* fr = (const ulonglong2*)(fch + e * 32);
#pragma unroll
        for (int p4 = 0; p4 < 4; p4++) {
            ulonglong2 ww = fr[p4];
            acc[2 * p4]     = fma2(pe2, ww.x, acc[2 * p4]);
            acc[2 * p4 + 1] = fma2(pe2, ww.y, acc[2 * p4 + 1]);
        }
    }

    if (valid) {
        float* op = out + 32ll * face + 16 * h;
#pragma unroll
        for (int p4 = 0; p4 < 4; p4++) {
            float2 a = unpack2(acc[2 * p4]);
            float2 b = unpack2(acc[2 * p4 + 1]);
            *(float4*)(op + 4 * p4) = make_float4(a.x, a.y, b.x, b.y);
        }
    }
}

extern "C" void kernel_launch(void* const* d_in, const int* in_sizes, int n_in,
                              void* d_out, int out_size) {
    const float* node  = (const float*)d_in[0];
    const int*   fids  = (const int*)d_in[1];
    const float* w_in  = (const float*)d_in[2];
    const float* b_in  = (const float*)d_in[3];
    const float* w_out = (const float*)d_in[4];
    const float* b_out = (const float*)d_in[5];
    const float* fc_w  = (const float*)d_in[6];
    const float* fc_b  = (const float*)d_in[7];
    const float* fco_w = (const float*)d_in[8];
    const float* fco_b = (const float*)d_in[9];

    int F = in_sizes[1] / 4;

    prep_kernel<<<1, 1024>>>(w_in, b_in, w_out, b_out, fc_w, fc_b, fco_w, fco_b);

    void* g_addr = nullptr;
    cudaGetSymbolAddress(&g_addr, g_pack);
    cudaMemcpyToSymbolAsync(c_pack, g_addr, PACK_N * sizeof(float), 0,
                            cudaMemcpyDeviceToDevice, 0);

    int blocks = (F + 63) / 64;
    face_kernel<<<blocks, 128>>>(node, fids, (float*)d_out, F);
}

// round 5
// speedup vs baseline: 1.5381x; 1.3218x over previous
#include <cuda_runtime.h>

// PlaneEmbeddingNetwork, R5: 3-kernel pipeline.
// K1: per-NODE qkv projection (8x reuse across faces) -> g_qkv[node][head][24]
// K2: per-face attention + fused-W2 (col-split) + relu + mean-pool -> g_pooled
// K3: fco GEMM, 4 faces per thread (weight loads amortized x4) -> out
// All heavy math in packed fp32 FMA (fma.rn.f32x2); weights from shared memory.

typedef unsigned long long u64;

__device__ __forceinline__ u64 fma2(u64 a, u64 b, u64 c) {
    u64 d;
    asm("fma.rn.f32x2 %0, %1, %2, %3;" : "=l"(d) : "l"(a), "l"(b), "l"(c));
    return d;
}
__device__ __forceinline__ u64 pack2(float x, float y) {
    u64 r;
    asm("mov.b64 %0, {%1, %2};" : "=l"(r) : "f"(x), "f"(y));
    return r;
}
__device__ __forceinline__ float2 unpack2(u64 v) {
    float2 f;
    asm("mov.b64 {%0, %1}, %2;" : "=f"(f.x), "=f"(f.y) : "l"(v));
    return f;
}
__device__ __forceinline__ float getc(float4 v, int c) {
    return c == 0 ? v.x : (c == 1 ? v.y : (c == 2 ? v.z : v.w));
}

// Static scratch (allocation-free rule): sized for the fixed problem shapes.
__device__ __align__(16) float g_qkv[250000 * 48];     // [node][head][q8,k8,v8]
__device__ __align__(16) float g_pooled[500000 * 32];  // [face][32]
__device__ __align__(16) float g_W2f[512];             // fused w_out @ fc_w
__device__ __align__(16) float g_b2f[32];              // fc_b + b_out @ fc_w

// ---------------------------------------------------------------------------
__global__ void prep_kernel(const float* __restrict__ w_out, const float* __restrict__ b_out,
                            const float* __restrict__ fc_w, const float* __restrict__ fc_b) {
    int i = threadIdx.x;
    if (i < 512) {
        int d = i >> 5, j = i & 31;
        float s = 0.f;
#pragma unroll
        for (int e = 0; e < 16; e++) s += w_out[d * 16 + e] * fc_w[e * 32 + j];
        g_W2f[i] = s;
    }
    if (i < 32) {
        float s = fc_b[i];
#pragma unroll
        for (int e = 0; e < 16; e++) s += b_out[e] * fc_w[e * 32 + i];
        g_b2f[i] = s;
    }
}

// ---------------------------------------------------------------------------
// K1: thread = (node-pair, head). Computes qkv (own head, 24 cols) for 2 nodes.
__global__ void __launch_bounds__(128)
qkv_kernel(const float* __restrict__ node, const float* __restrict__ w_in,
           const float* __restrict__ b_in, int Nn) {
    __shared__ __align__(16) float s_w[768];
    __shared__ __align__(16) float s_b[48];
    int tid = threadIdx.x;
    for (int i = tid; i < 768; i += 128) s_w[i] = w_in[i];
    if (tid < 48) s_b[tid] = b_in[tid];
    __syncthreads();

    int gi = blockIdx.x * 128 + tid;
    int h = gi & 1;
    int g = gi >> 1;              // node-pair index
    int npairs = Nn >> 1;
    bool valid = g < npairs;
    if (!valid) g = npairs - 1;
    int n0 = 2 * g, n1 = 2 * g + 1;

    float4 X0[4], X1[4];
    {
        const float4* r0 = (const float4*)(node + 16ll * n0);
        const float4* r1 = (const float4*)(node + 16ll * n1);
        X0[0] = r0[0]; X0[1] = r0[1]; X0[2] = r0[2]; X0[3] = r0[3];
        X1[0] = r1[0]; X1[1] = r1[1]; X1[2] = r1[2]; X1[3] = r1[3];
    }

    // accs: [q0..3, k0..3, v0..3] u64 pairs per node
    u64 a0[12], a1[12];
    {
        const u64* bq = (const u64*)(s_b + 8 * h);
        const u64* bk = (const u64*)(s_b + 16 + 8 * h);
        const u64* bv = (const u64*)(s_b + 32 + 8 * h);
#pragma unroll
        for (int j = 0; j < 4; j++) {
            a0[j] = bq[j];     a1[j] = bq[j];
            a0[4 + j] = bk[j]; a1[4 + j] = bk[j];
            a0[8 + j] = bv[j]; a1[8 + j] = bv[j];
        }
    }
#pragma unroll
    for (int d = 0; d < 16; d++) {
        const float* w = s_w + d * 48 + 8 * h;
        ulonglong2 wqa = *(const ulonglong2*)(w);
        ulonglong2 wqb = *(const ulonglong2*)(w + 4);
        ulonglong2 wka = *(const ulonglong2*)(w + 16);
        ulonglong2 wkb = *(const ulonglong2*)(w + 20);
        ulonglong2 wva = *(const ulonglong2*)(w + 32);
        ulonglong2 wvb = *(const ulonglong2*)(w + 36);
        float x0 = getc(X0[d >> 2], d & 3);
        float x1 = getc(X1[d >> 2], d & 3);
        u64 p0 = pack2(x0, x0), p1 = pack2(x1, x1);
        a0[0] = fma2(p0, wqa.x, a0[0]);  a0[1] = fma2(p0, wqa.y, a0[1]);
        a0[2] = fma2(p0, wqb.x, a0[2]);  a0[3] = fma2(p0, wqb.y, a0[3]);
        a0[4] = fma2(p0, wka.x, a0[4]);  a0[5] = fma2(p0, wka.y, a0[5]);
        a0[6] = fma2(p0, wkb.x, a0[6]);  a0[7] = fma2(p0, wkb.y, a0[7]);
        a0[8] = fma2(p0, wva.x, a0[8]);  a0[9] = fma2(p0, wva.y, a0[9]);
        a0[10] = fma2(p0, wvb.x, a0[10]); a0[11] = fma2(p0, wvb.y, a0[11]);
        a1[0] = fma2(p1, wqa.x, a1[0]);  a1[1] = fma2(p1, wqa.y, a1[1]);
        a1[2] = fma2(p1, wqb.x, a1[2]);  a1[3] = fma2(p1, wqb.y, a1[3]);
        a1[4] = fma2(p1, wka.x, a1[4]);  a1[5] = fma2(p1, wka.y, a1[5]);
        a1[6] = fma2(p1, wkb.x, a1[6]);  a1[7] = fma2(p1, wkb.y, a1[7]);
        a1[8] = fma2(p1, wva.x, a1[8]);  a1[9] = fma2(p1, wva.y, a1[9]);
        a1[10] = fma2(p1, wvb.x, a1[10]); a1[11] = fma2(p1, wvb.y, a1[11]);
    }

    if (valid) {
        float* o0 = g_qkv + (2ll * n0 + h) * 24;
        float* o1 = g_qkv + (2ll * n1 + h) * 24;
#pragma unroll
        for (int j = 0; j < 6; j++) {
            float2 x = unpack2(a0[2 * j]), y = unpack2(a0[2 * j + 1]);
            ((float4*)o0)[j] = make_float4(x.x, x.y, y.x, y.y);
        }
#pragma unroll
        for (int j = 0; j < 6; j++) {
            float2 x = unpack2(a1[2 * j]), y = unpack2(a1[2 * j + 1]);
            ((float4*)o1)[j] = make_float4(x.x, x.y, y.x, y.y);
        }
    }
}

// ---------------------------------------------------------------------------
// K2: thread = (face, head) on adjacent lanes. Attention + W2(col-split) + pool.
__global__ void __launch_bounds__(128)
face_kernel(const int* __restrict__ fids, int F) {
    __shared__ __align__(16) float sW2[512];
    __shared__ __align__(16) float sb2[32];
    int tid = threadIdx.x;
    for (int i = tid; i < 512; i += 128) sW2[i] = g_W2f[i];
    if (tid < 32) sb2[tid] = g_b2f[tid];
    __syncthreads();

    int gi = blockIdx.x * 128 + tid;
    int face = gi >> 1;
    int h = gi & 1;
    bool valid = face < F;
    if (!valid) face = F - 1;

    // gather own-head q,k,v for 4 tokens (24 floats each, 96B contiguous)
    int4 I = *(const int4*)(fids + 4ll * face);
    int ids[4] = {I.x, I.y, I.z, I.w};
    u64 q2[4][4], k2[4][4], v2[4][4];
#pragma unroll
    for (int t = 0; t < 4; t++) {
        const float4* p = (const float4*)(g_qkv + (2ll * ids[t] + h) * 24);
        float4 qa = p[0], qb = p[1], ka = p[2], kb = p[3], va = p[4], vb = p[5];
        q2[t][0] = pack2(qa.x, qa.y); q2[t][1] = pack2(qa.z, qa.w);
        q2[t][2] = pack2(qb.x, qb.y); q2[t][3] = pack2(qb.z, qb.w);
        k2[t][0] = pack2(ka.x, ka.y); k2[t][1] = pack2(ka.z, ka.w);
        k2[t][2] = pack2(kb.x, kb.y); k2[t][3] = pack2(kb.z, kb.w);
        v2[t][0] = pack2(va.x, va.y); v2[t][1] = pack2(va.z, va.w);
        v2[t][2] = pack2(vb.x, vb.y); v2[t][3] = pack2(vb.z, vb.w);
    }

    // scores + softmax (own head, 4x4)
    float att[4][4];
    const float RS = 0.35355339059327373f;  // 1/sqrt(8)
#pragma unroll
    for (int qi = 0; qi < 4; qi++) {
#pragma unroll
        for (int ki = 0; ki < 4; ki++) {
            u64 a = fma2(q2[qi][0], k2[ki][0], 0ull);
            a = fma2(q2[qi][1], k2[ki][1], a);
            a = fma2(q2[qi][2], k2[ki][2], a);
            a = fma2(q2[qi][3], k2[ki][3], a);
            float2 p = unpack2(a);
            att[qi][ki] = (p.x + p.y) * RS;
        }
        float m = fmaxf(fmaxf(att[qi][0], att[qi][1]), fmaxf(att[qi][2], att[qi][3]));
        float e0 = __expf(att[qi][0] - m);
        float e1 = __expf(att[qi][1] - m);
        float e2 = __expf(att[qi][2] - m);
        float e3 = __expf(att[qi][3] - m);
        float inv = 1.0f / (e0 + e1 + e2 + e3);
        att[qi][0] = e0 * inv; att[qi][1] = e1 * inv;
        att[qi][2] = e2 * inv; att[qi][3] = e3 * inv;
    }

    // o = attn @ v : own-head 8 dims, all 4 query tokens
    u64 o2[4][4];
#pragma unroll
    for (int qi = 0; qi < 4; qi++) {
#pragma unroll
        for (int j = 0; j < 4; j++) o2[qi][j] = 0ull;
#pragma unroll
        for (int s = 0; s < 4; s++) {
            u64 a2 = pack2(att[qi][s], att[qi][s]);
#pragma unroll
            for (int j = 0; j < 4; j++) o2[qi][j] = fma2(a2, v2[s][j], o2[qi][j]);
        }
    }

    // exchange with partner lane: assemble full 16-dim o per token
    u64 lo[4][4], hi[4][4];   // dims 0-7 (head0) and 8-15 (head1)
#pragma unroll
    for (int t = 0; t < 4; t++)
#pragma unroll
        for (int j = 0; j < 4; j++) {
            u64 rcv = __shfl_xor_sync(0xffffffffu, o2[t][j], 1);
            lo[t][j] = h ? rcv : o2[t][j];
            hi[t][j] = h ? o2[t][j] : rcv;
        }

    // W2 col-split: this thread computes cols [16h, 16h+16) for ALL 4 tokens
    u64 acc[4][8];
    {
        const u64* bb = (const u64*)(sb2 + 16 * h);
#pragma unroll
        for (int t = 0; t < 4; t++)
#pragma unroll
            for (int j = 0; j < 8; j++) acc[t][j] = bb[j];
    }
#pragma unroll
    for (int d = 0; d < 16; d++) {
        const ulonglong2* wr = (const ulonglong2*)(sW2 + d * 32 + 16 * h);
        ulonglong2 wa = wr[0], wb = wr[1], wc = wr[2], wd = wr[3];
#pragma unroll
        for (int t = 0; t < 4; t++) {
            float ov;
            if (d < 8) {
                float2 p = unpack2(lo[t][d >> 1]);
                ov = (d & 1) ? p.y : p.x;
            } else {
                float2 p = unpack2(hi[t][(d - 8) >> 1]);
                ov = (d & 1) ? p.y : p.x;
            }
            u64 op = pack2(ov, ov);
            acc[t][0] = fma2(op, wa.x, acc[t][0]);
            acc[t][1] = fma2(op, wa.y, acc[t][1]);
            acc[t][2] = fma2(op, wb.x, acc[t][2]);
            acc[t][3] = fma2(op, wb.y, acc[t][3]);
            acc[t][4] = fma2(op, wc.x, acc[t][4]);
            acc[t][5] = fma2(op, wc.y, acc[t][5]);
            acc[t][6] = fma2(op, wd.x, acc[t][6]);
            acc[t][7] = fma2(op, wd.y, acc[t][7]);
        }
    }

    // relu + mean over 4 tokens (all local!), store own 16-col half of pooled
    if (valid) {
        float* op = g_pooled + 32ll * face + 16 * h;
#pragma unroll
        for (int j = 0; j < 4; j++) {
            float rx0 = 0.f, ry0 = 0.f, rx1 = 0.f, ry1 = 0.f;
#pragma unroll
            for (int t = 0; t < 4; t++) {
                float2 a = unpack2(acc[t][2 * j]);
                float2 b = unpack2(acc[t][2 * j + 1]);
                rx0 += fmaxf(a.x, 0.f); ry0 += fmaxf(a.y, 0.f);
                rx1 += fmaxf(b.x, 0.f); ry1 += fmaxf(b.y, 0.f);
            }
            ((float4*)op)[j] = make_float4(rx0 * 0.25f, ry0 * 0.25f,
                                           rx1 * 0.25f, ry1 * 0.25f);
        }
    }
}

// ---------------------------------------------------------------------------
// K3: fco GEMM. Block = 128 threads <-> 256 faces. Thread = 4 faces x 16 cols.
__global__ void __launch_bounds__(128)
fco_kernel(const float* __restrict__ fco_w, const float* __restrict__ fco_b,
           float* __restrict__ out, int F) {
    __shared__ float ps[256][33];            // padded: bank = (face + k) % 32
    __shared__ __align__(16) float ws[1024];
    __shared__ __align__(16) float bs[32];
    int tid = threadIdx.x;
    for (int i = tid; i < 1024; i += 128) ws[i] = fco_w[i];
    if (tid < 32) bs[tid] = fco_b[tid];

    int base = blockIdx.x * 256;
    for (int r = tid; r < 256; r += 128) {
        int f = base + r; if (f >= F) f = F - 1;
        const float4* src = (const float4*)(g_pooled + 32ll * f);
#pragma unroll
        for (int c4 = 0; c4 < 8; c4++) {
            float4 v = src[c4];
            ps[r][c4 * 4 + 0] = v.x; ps[r][c4 * 4 + 1] = v.y;
            ps[r][c4 * 4 + 2] = v.z; ps[r][c4 * 4 + 3] = v.w;
        }
    }
    __syncthreads();

    int fg = tid >> 1;        // 0..63 -> 4 faces each
    int half = tid & 1;
    int r0 = fg * 4;

    u64 acc[4][8];
    {
        const u64* bb = (const u64*)(bs + 16 * half);
#pragma unroll
        for (int i = 0; i < 4; i++)
#pragma unroll
            for (int j = 0; j < 8; j++) acc[i][j] = bb[j];
    }
#pragma unroll 8
    for (int k = 0; k < 32; k++) {
        const ulonglong2* wr = (const ulonglong2*)(ws + k * 32 + 16 * half);
        ulonglong2 wa = wr[0], wb = wr[1], wc = wr[2], wd = wr[3];
#pragma unroll
        for (int i = 0; i < 4; i++) {
            float a = ps[r0 + i][k];
            u64 ap = pack2(a, a);
            acc[i][0] = fma2(ap, wa.x, acc[i][0]);
            acc[i][1] = fma2(ap, wa.y, acc[i][1]);
            acc[i][2] = fma2(ap, wb.x, acc[i][2]);
            acc[i][3] = fma2(ap, wb.y, acc[i][3]);
            acc[i][4] = fma2(ap, wc.x, acc[i][4]);
            acc[i][5] = fma2(ap, wc.y, acc[i][5]);
            acc[i][6] = fma2(ap, wd.x, acc[i][6]);
            acc[i][7] = fma2(ap, wd.y, acc[i][7]);
        }
    }

#pragma unroll
    for (int i = 0; i < 4; i++) {
        int f = base + r0 + i;
        if (f < F) {
            float* op = out + 32ll * f + 16 * half;
#pragma unroll
            for (int j = 0; j < 4; j++) {
                float2 a = unpack2(acc[i][2 * j]);
                float2 b = unpack2(acc[i][2 * j + 1]);
                ((float4*)op)[j] = make_float4(a.x, a.y, b.x, b.y);
            }
        }
    }
}

// ---------------------------------------------------------------------------
extern "C" void kernel_launch(void* const* d_in, const int* in_sizes, int n_in,
                              void* d_out, int out_size) {
    const float* node  = (const float*)d_in[0];
    const int*   fids  = (const int*)d_in[1];
    const float* w_in  = (const float*)d_in[2];
    const float* b_in  = (const float*)d_in[3];
    const float* w_out = (const float*)d_in[4];
    const float* b_out = (const float*)d_in[5];
    const float* fc_w  = (const float*)d_in[6];
    const float* fc_b  = (const float*)d_in[7];
    const float* fco_w = (const float*)d_in[8];
    const float* fco_b = (const float*)d_in[9];

    int Nn = in_sizes[0] / 16;   // 250000
    int F  = in_sizes[1] / 4;    // 500000

    prep_kernel<<<1, 512>>>(w_out, b_out, fc_w, fc_b);

    int k1_threads = Nn;         // 2 per node-pair * Nn/2
    qkv_kernel<<<(k1_threads + 127) / 128, 128>>>(node, w_in, b_in, Nn);

    long long k2_threads = 2ll * F;
    face_kernel<<<(int)((k2_threads + 127) / 128), 128>>>(fids, F);

    fco_kernel<<<(F + 255) / 256, 128>>>(fco_w, fco_b, (float*)d_out, F);
}